// round 13
// baseline (speedup 1.0000x reference)
#include <cuda_runtime.h>
#include <cuda_bf16.h>
#include <math.h>
#include <stdint.h>

#define NEGV (-10000.0f)
#define LOG2E 1.44269504088896340736f

// ---------------- K2 smem byte offsets ----------------
#define XVT_B    0
#define PE2H_B   0
#define PE2L_B   10240
#define TNH_B    20480
#define TNL_B    30720
#define A_HI_B   67584
#define A_LO_B   100352
#define W_HI_B   133120
#define W_LO_B   165888
#define SK_B     198656
#define SG1_B    199168
#define SB1_B    199680
#define SG2_B    200192
#define SB2_B    200704
#define SBI1_B   201216
#define SBI2_B   201728
#define SPE1_B   202240
#define SPIJ_B   202752
#define SXO_B    204800
#define SP_B     205312
#define SP2_B    207360
#define SDN_B    209408
#define K2_SMEM  211456

// ---------------- K3 smem byte offsets ----------------
#define K3_A1H   0
#define K3_A1L   10240
#define K3_B1H   20480
#define K3_B1L   30720
#define K3_B2H   40960
#define K3_B2L   49152
#define K3_SPIJ  57344
#define K3_SNORM 59392
#define K3_SS    59904
#define K3_SPAD  60416
#define K3_SA    60928
#define K3_SE1C  61056
#define K3_SX1B  61184
#define K3_SX2V  61312
#define K3_SMEM  61440

// ---------------- device scratch ----------------
__device__ float g_q[16*128*128];
__device__ float g_k[16*128*128];
__device__ float g_v[16*128*128];
__device__ float g_wqT[64*128];
__device__ float g_wkT[64*128];
__device__ float g_wvT[64*128];
__device__ float g_avec[16*128*32];
__device__ float g_bvec[16*128*32];
__device__ uint32_t g_w1hi[8192];
__device__ uint32_t g_w1lo[8192];
__device__ uint32_t g_w2hi[8192];
__device__ uint32_t g_w2lo[8192];
__device__ uint32_t g_x1hi[2048];
__device__ uint32_t g_x1lo[2048];
__device__ uint32_t g_pe2hi[2560];
__device__ uint32_t g_pe2lo[2560];
__device__ uint32_t g_e2hi[2560];
__device__ uint32_t g_e2lo[2560];

// ---------------- helpers ----------------
__device__ __forceinline__ float wsum(float v){
#pragma unroll
    for (int k = 16; k > 0; k >>= 1) v += __shfl_xor_sync(0xffffffffu, v, k);
    return v;
}
__device__ __forceinline__ float qsum(float v){
    v += __shfl_xor_sync(0xffffffffu, v, 1);
    v += __shfl_xor_sync(0xffffffffu, v, 2);
    return v;
}
__device__ __forceinline__ uint32_t smem_u32(const void* p){
    uint32_t a;
    asm("{ .reg .u64 t; cvta.to.shared.u64 t, %1; cvt.u32.u64 %0, t; }" : "=r"(a) : "l"(p));
    return a;
}
__device__ __forceinline__ uint32_t swz(int row, int kb){
    return (uint32_t)(row*256 + ((kb & 0xF0) ^ ((row & 7) << 4)) + (kb & 15));
}
__device__ __forceinline__ float ex2(float x){
    float r; asm("ex2.approx.ftz.f32 %0, %1;" : "=f"(r) : "f"(x)); return r;
}
__device__ __forceinline__ void barp(int id){
    asm volatile("bar.sync %0, 64;" :: "r"(id) : "memory");
}
__device__ __forceinline__ void split2(float x, float y, uint32_t &hi, uint32_t &lo){
    uint32_t h;
    asm("cvt.rn.bf16x2.f32 %0, %1, %2;" : "=r"(h) : "f"(y), "f"(x));
    float xh = __uint_as_float(h << 16);
    float yh = __uint_as_float(h & 0xFFFF0000u);
    asm("cvt.rn.bf16x2.f32 %0, %1, %2;" : "=r"(lo) : "f"(y - yh), "f"(x - xh));
    hi = h;
}
__device__ __forceinline__ void ldsm4(uint32_t a[4], uint32_t addr){
    asm volatile("ldmatrix.sync.aligned.m8n8.x4.shared.b16 {%0,%1,%2,%3}, [%4];"
        : "=r"(a[0]), "=r"(a[1]), "=r"(a[2]), "=r"(a[3]) : "r"(addr));
}
__device__ __forceinline__ void mma16816(float d[4], const uint32_t a[4], const uint32_t b[2]){
    asm volatile("mma.sync.aligned.m16n8k16.row.col.f32.bf16.bf16.f32 "
        "{%0,%1,%2,%3}, {%4,%5,%6,%7}, {%8,%9}, {%0,%1,%2,%3};"
        : "+f"(d[0]), "+f"(d[1]), "+f"(d[2]), "+f"(d[3])
        : "r"(a[0]), "r"(a[1]), "r"(a[2]), "r"(a[3]), "r"(b[0]), "r"(b[1]));
}

// inner B-load + MMA block for one K-step of gemm128q
__device__ __forceinline__ void g128_step(uint32_t Bh, uint32_t Bl, uint32_t bo,
                                          const uint32_t ah[4], const uint32_t al_[4],
                                          float d[8][4]){
#pragma unroll
    for (int t2 = 0; t2 < 4; t2++){
        uint32_t bh[4], bl[4];
        ldsm4(bh, Bh + bo + (uint32_t)(t2*4096));
        ldsm4(bl, Bl + bo + (uint32_t)(t2*4096));
        mma16816(d[2*t2],   ah,  bh);
        mma16816(d[2*t2+1], ah,  bh+2);
        mma16816(d[2*t2],   ah,  bl);
        mma16816(d[2*t2+1], ah,  bl+2);
        mma16816(d[2*t2],   al_, bh);
        mma16816(d[2*t2+1], al_, bh+2);
    }
}

// K2 quadrant GEMM with manual A-fragment double-buffering (software pipeline)
__device__ __forceinline__ void gemm128q(uint32_t Ah, uint32_t Al, uint32_t Bh, uint32_t Bl,
                                         int r, int cb, int lane, float d[8][4]){
#pragma unroll
    for (int t = 0; t < 8; t++){ d[t][0]=0.f; d[t][1]=0.f; d[t][2]=0.f; d[t][3]=0.f; }
    const uint32_t aro = (uint32_t)((r*16 + (lane&15))*256);
    const uint32_t aox = (uint32_t)((lane&7)<<4);
    const uint32_t akx = (uint32_t)(lane&16);
    const uint32_t bro = (uint32_t)((cb + (lane&7) + ((lane>>4)<<3))*256);
    const uint32_t bkx = (uint32_t)((lane&8)<<1);

    uint32_t ah0[4], al0[4], ah1[4], al1[4];
    ldsm4(ah0, Ah + aro + ((0u + akx) ^ aox));
    ldsm4(al0, Al + aro + ((0u + akx) ^ aox));
#pragma unroll
    for (int kk2 = 0; kk2 < 4; kk2++){
        uint32_t ka1 = (uint32_t)((2*kk2 + 1)*32);
        ldsm4(ah1, Ah + aro + ((ka1 + akx) ^ aox));
        ldsm4(al1, Al + aro + ((ka1 + akx) ^ aox));
        g128_step(Bh, Bl, bro + (((uint32_t)(2*kk2*32) + bkx) ^ aox), ah0, al0, d);
        if (kk2 < 3){
            uint32_t ka2 = (uint32_t)((2*kk2 + 2)*32);
            ldsm4(ah0, Ah + aro + ((ka2 + akx) ^ aox));
            ldsm4(al0, Al + aro + ((ka2 + akx) ^ aox));
        }
        g128_step(Bh, Bl, bro + ((ka1 + bkx) ^ aox), ah1, al1, d);
    }
}

// K2 quadrant small-K GEMM: K=32, 80B-stride tiles.
__device__ __forceinline__ void gemm32q(uint32_t Ah, uint32_t Al, uint32_t Bh, uint32_t Bl,
                                        int r, int cb, int lane, float d[8][4]){
#pragma unroll
    for (int t = 0; t < 8; t++){ d[t][0]=0.f; d[t][1]=0.f; d[t][2]=0.f; d[t][3]=0.f; }
    const uint32_t aro = (uint32_t)((r*16 + (lane&15))*80 + (lane&16));
    const uint32_t bro = (uint32_t)((cb + (lane&7) + ((lane>>4)<<3))*80 + ((lane&8)<<1));
#pragma unroll
    for (int kk = 0; kk < 2; kk++){
        uint32_t ah[4], al_[4];
        ldsm4(ah,  Ah + aro + (uint32_t)(kk*32));
        ldsm4(al_, Al + aro + (uint32_t)(kk*32));
#pragma unroll
        for (int t2 = 0; t2 < 4; t2++){
            uint32_t bh[4], bl[4];
            ldsm4(bh, Bh + bro + (uint32_t)(kk*32 + t2*1280));
            ldsm4(bl, Bl + bro + (uint32_t)(kk*32 + t2*1280));
            mma16816(d[2*t2],   ah,  bh);
            mma16816(d[2*t2+1], ah,  bh+2);
            mma16816(d[2*t2],   ah,  bl);
            mma16816(d[2*t2+1], ah,  bl+2);
            mma16816(d[2*t2],   al_, bh);
            mma16816(d[2*t2+1], al_, bh+2);
        }
    }
}

// K3 full-width K=32 GEMM (8 warps, 16 rows each, all 128 cols)
__device__ __forceinline__ void gemm32(uint32_t Ah, uint32_t Al, uint32_t Bh, uint32_t Bl,
                                       int warp, int lane, float d[16][4]){
#pragma unroll
    for (int t = 0; t < 16; t++){ d[t][0]=0.f; d[t][1]=0.f; d[t][2]=0.f; d[t][3]=0.f; }
    const uint32_t aro = (uint32_t)((warp*16 + (lane&15))*80 + (lane&16));
    const uint32_t bro = (uint32_t)(((lane&7) + ((lane>>4)<<3))*80 + ((lane&8)<<1));
#pragma unroll
    for (int kk = 0; kk < 2; kk++){
        uint32_t ah[4], al_[4];
        ldsm4(ah,  Ah + aro + (uint32_t)(kk*32));
        ldsm4(al_, Al + aro + (uint32_t)(kk*32));
#pragma unroll
        for (int t2 = 0; t2 < 8; t2++){
            uint32_t bh[4], bl[4];
            ldsm4(bh, Bh + bro + (uint32_t)(kk*32 + t2*1280));
            ldsm4(bl, Bl + bro + (uint32_t)(kk*32 + t2*1280));
            mma16816(d[2*t2],   ah,  bh);
            mma16816(d[2*t2+1], ah,  bh+2);
            mma16816(d[2*t2],   ah,  bl);
            mma16816(d[2*t2+1], ah,  bl+2);
            mma16816(d[2*t2],   al_, bh);
            mma16816(d[2*t2+1], al_, bh+2);
        }
    }
}

// K3 MMA2 with A from registers
__device__ __forceinline__ void mma2_regA(const float y[16][4], uint32_t Bh, uint32_t Bl,
                                          int lane, float d2[4][4]){
#pragma unroll
    for (int t = 0; t < 4; t++){ d2[t][0]=0.f; d2[t][1]=0.f; d2[t][2]=0.f; d2[t][3]=0.f; }
    const uint32_t aox = (uint32_t)((lane&7)<<4);
    const uint32_t bro = (uint32_t)(((lane&7) + ((lane>>4)<<3))*256);
    const uint32_t bkx = (uint32_t)((lane&8)<<1);
#pragma unroll
    for (int kt = 0; kt < 8; kt++){
        uint32_t ah[4], al_[4];
        split2(y[2*kt][0],   y[2*kt][1],   ah[0], al_[0]);
        split2(y[2*kt][2],   y[2*kt][3],   ah[1], al_[1]);
        split2(y[2*kt+1][0], y[2*kt+1][1], ah[2], al_[2]);
        split2(y[2*kt+1][2], y[2*kt+1][3], ah[3], al_[3]);
        uint32_t bo = bro + (((uint32_t)(kt*32) + bkx) ^ aox);
#pragma unroll
        for (int t2 = 0; t2 < 2; t2++){
            uint32_t bh[4], bl[4];
            ldsm4(bh, Bh + bo + (uint32_t)(t2*4096));
            ldsm4(bl, Bl + bo + (uint32_t)(t2*4096));
            mma16816(d2[2*t2],   ah,  bh);
            mma16816(d2[2*t2+1], ah,  bh+2);
            mma16816(d2[2*t2],   ah,  bl);
            mma16816(d2[2*t2+1], ah,  bl+2);
            mma16816(d2[2*t2],   al_, bh);
            mma16816(d2[2*t2+1], al_, bh+2);
        }
    }
}

// ---------------- K0: weight prep ----------------
__global__ void k0_prep(const float* __restrict__ wq, const float* __restrict__ wk,
                        const float* __restrict__ wv, const float* __restrict__ w1,
                        const float* __restrict__ w2, const float* __restrict__ pe2,
                        const float* __restrict__ e2, const float* __restrict__ x1){
    int idx = blockIdx.x * blockDim.x + threadIdx.x;
    int stride = gridDim.x * blockDim.x;
    for (int t = idx; t < 16384; t += stride){
        int c = t >> 7, m = t & 127;
        uint32_t a = swz(c, m*2) >> 1;
        float v1 = w1[t];
        __nv_bfloat16 h1 = __float2bfloat16(v1);
        ((unsigned short*)g_w1hi)[a] = __bfloat16_as_ushort(h1);
        ((unsigned short*)g_w1lo)[a] = __bfloat16_as_ushort(__float2bfloat16(v1 - __bfloat162float(h1)));
        float v2 = w2[t] * LOG2E;
        __nv_bfloat16 h2 = __float2bfloat16(v2);
        ((unsigned short*)g_w2hi)[a] = __bfloat16_as_ushort(h2);
        ((unsigned short*)g_w2lo)[a] = __bfloat16_as_ushort(__float2bfloat16(v2 - __bfloat162float(h2)));
    }
    for (int t = idx; t < 4096; t += stride){
        int c = t >> 5, m = t & 31;
        uint32_t a80 = (uint32_t)(c*40 + m);
        float vp = pe2[t];
        __nv_bfloat16 hp = __float2bfloat16(vp);
        ((unsigned short*)g_pe2hi)[a80] = __bfloat16_as_ushort(hp);
        ((unsigned short*)g_pe2lo)[a80] = __bfloat16_as_ushort(__float2bfloat16(vp - __bfloat162float(hp)));
        float ve = e2[t];
        __nv_bfloat16 he = __float2bfloat16(ve);
        ((unsigned short*)g_e2hi)[a80] = __bfloat16_as_ushort(he);
        ((unsigned short*)g_e2lo)[a80] = __bfloat16_as_ushort(__float2bfloat16(ve - __bfloat162float(he)));
        int m2 = t >> 7, c2 = t & 127;
        uint32_t ax = swz(m2, c2*2) >> 1;
        float vx = x1[t];
        __nv_bfloat16 hx = __float2bfloat16(vx);
        ((unsigned short*)g_x1hi)[ax] = __bfloat16_as_ushort(hx);
        ((unsigned short*)g_x1lo)[ax] = __bfloat16_as_ushort(__float2bfloat16(vx - __bfloat162float(hx)));
    }
    for (int t = idx; t < 8192; t += stride){
        int c = t >> 6, d = t & 63;
        g_wqT[d*128 + c] = wq[t];
        g_wkT[d*128 + c] = wk[t];
        g_wvT[d*128 + c] = wv[t];
    }
}

// ---------------- K1: q,k,v projections ----------------
__global__ void __launch_bounds__(128) k1_qkv(const float* __restrict__ x,
                                              const float* __restrict__ bq,
                                              const float* __restrict__ bk,
                                              const float* __restrict__ bv){
    __shared__ float sx[64];
    int row = blockIdx.x;
    int c = threadIdx.x;
    if (c < 64) sx[c] = x[(size_t)row*64 + c];
    __syncthreads();
    float aq = bq[c], ak = bk[c], av = bv[c];
#pragma unroll 8
    for (int d = 0; d < 64; d++){
        float xv = sx[d];
        aq = fmaf(xv, g_wqT[d*128 + c], aq);
        ak = fmaf(xv, g_wkT[d*128 + c], ak);
        av = fmaf(xv, g_wvT[d*128 + c], av);
    }
    g_q[(size_t)row*128 + c] = aq;
    g_k[(size_t)row*128 + c] = ak;
    g_v[(size_t)row*128 + c] = av;
}

// ---------------- K2: fused attention per (n,i) ----------------
__global__ void __launch_bounds__(512) k2_attn(
    const float* __restrict__ U, const float* __restrict__ p,
    const float* __restrict__ ln1_g, const float* __restrict__ ln1_b,
    const float* __restrict__ b1,
    const float* __restrict__ ln2_g, const float* __restrict__ ln2_b,
    const float* __restrict__ b2,
    const float* __restrict__ pe1, const float* __restrict__ e1,
    float* __restrict__ xout)
{
    extern __shared__ char sm8[];
    float*  sxvT = (float*)(sm8 + XVT_B);
    float*  sk   = (float*)(sm8 + SK_B);
    float*  sg1  = (float*)(sm8 + SG1_B);
    float*  sb1v = (float*)(sm8 + SB1_B);
    float*  sg2  = (float*)(sm8 + SG2_B);
    float*  sb2v = (float*)(sm8 + SB2_B);
    float*  sbi1 = (float*)(sm8 + SBI1_B);
    float*  sbi2 = (float*)(sm8 + SBI2_B);
    float*  spe1 = (float*)(sm8 + SPE1_B);
    float*  spij = (float*)(sm8 + SPIJ_B);
    float*  sxo  = (float*)(sm8 + SXO_B);
    float2* sp   = (float2*)(sm8 + SP_B);
    float*  spart= (float*)(sm8 + SP_B);
    float2* sp2  = (float2*)(sm8 + SP2_B);
    float2* sdn  = (float2*)(sm8 + SDN_B);

    const uint32_t sbase = smem_u32(sm8);
    const uint32_t Ah = sbase + A_HI_B, Al = sbase + A_LO_B;
    const uint32_t Wh = sbase + W_HI_B, Wl = sbase + W_LO_B;
    const int tid = threadIdx.x;
    const int lane = tid & 31, warp = tid >> 5;
    const int r = warp & 7, ch = warp >> 3;
    const int cb = ch*64;
    const int bid = r + 1;
    const int n = blockIdx.x >> 7, i = blockIdx.x & 127;
    const int g4 = lane & 3;
    const int rowA = r*16 + (lane>>2), rowB = rowA + 8;

    const float* Ub = U + (size_t)blockIdx.x * 16384;
    asm volatile("prefetch.global.L2 [%0];" :: "l"(Ub + (tid << 5)));

    // ----- stage 0 -----
    if (tid < 128){
        size_t rowk = (size_t)(n*128 + i);
        sk[tid]   = g_k[rowk*128 + tid];
        sg1[tid]  = ln1_g[tid];  sb1v[tid] = ln1_b[tid];
        sg2[tid]  = ln2_g[tid];  sb2v[tid] = ln2_b[tid];
        sbi1[tid] = b1[tid];     sbi2[tid] = b2[tid] * LOG2E;
        spe1[tid] = pe1[tid];
        int j = tid;
        float4 pi = *(const float4*)(p + (size_t)(n*128 + i)*4);
        float4 pj = *(const float4*)(p + (size_t)(n*128 + j)*4);
        spij[j*4+0] = pi.x - pj.x;
        spij[j*4+1] = pi.y - pj.y;
        spij[j*4+2] = pi.z - pj.z;
        spij[j*4+3] = pi.w - pj.w;
    }
    for (int t = tid; t < 2560; t += 512){
        ((uint32_t*)(sm8 + PE2H_B))[t] = g_pe2hi[t];
        ((uint32_t*)(sm8 + PE2L_B))[t] = g_pe2lo[t];
    }
    {
        const uint4* whi = (const uint4*)g_w1hi;
        const uint4* wlo = (const uint4*)g_w1lo;
        uint4* dhi = (uint4*)(sm8 + W_HI_B);
        uint4* dlo = (uint4*)(sm8 + W_LO_B);
#pragma unroll
        for (int t = 0; t < 4; t++){
            dhi[tid + 512*t] = whi[tid + 512*t];
            dlo[tid + 512*t] = wlo[tid + 512*t];
        }
    }
    const bool pad_i = (p[(size_t)(n*128 + i)*4] == 0.0f);
    __syncthreads();                                            // FULL B1

    // ----- U register prefetch -----
    float rU[8][4];
#pragma unroll
    for (int t = 0; t < 8; t++){
        int c0 = cb + t*8 + g4*2;
        float2 uA = *(const float2*)(Ub + rowA*128 + c0);
        float2 uB = *(const float2*)(Ub + rowB*128 + c0);
        rU[t][0] = uA.x; rU[t][1] = uA.y;
        rU[t][2] = uB.x; rU[t][3] = uB.y;
    }

    // ----- tn: pair-owned rows -----
    {
        float4 pe1r = ((const float4*)spe1)[lane];
#pragma unroll 1
        for (int rr = 0; rr < 8; rr++){
            int jj = r*16 + ch*8 + rr;
            float4 pd = *(const float4*)(spij + jj*4);
            float t = pd.x*pe1r.x + pd.y*pe1r.y + pd.z*pe1r.z + pd.w*pe1r.w;
            float s1 = t, s2v = t*t;
#pragma unroll
            for (int k = 16; k > 0; k >>= 1){
                s1  += __shfl_xor_sync(0xffffffffu, s1,  k);
                s2v += __shfl_xor_sync(0xffffffffu, s2v, k);
            }
            float mu = s1 * (1.0f/32.0f);
            float var = fmaxf(s2v*(1.0f/32.0f) - mu*mu, 0.0f);
            float tn = fmaxf((t - mu) * rsqrtf(var + 1e-5f), 0.0f);
            float tn1 = __shfl_down_sync(0xffffffffu, tn, 1);
            if (!(lane & 1)){
                uint32_t hi, lo;
                split2(tn, tn1, hi, lo);
                *(uint32_t*)(sm8 + TNH_B + jj*80 + lane*2) = hi;
                *(uint32_t*)(sm8 + TNL_B + jj*80 + lane*2) = lo;
            }
        }
    }
    barp(bid);                                                  // pair B2

    // ----- GEMM0 -----
    float d[8][4];
    gemm32q(sbase + TNH_B, sbase + TNL_B, sbase + PE2H_B, sbase + PE2L_B, r, cb, lane, d);

    // ----- epi0 stats -----
    {
        float s1A = 0, s2A = 0, s1B = 0, s2B = 0;
#pragma unroll
        for (int t = 0; t < 8; t++){
            s1A += d[t][0] + d[t][1]; s2A += d[t][0]*d[t][0] + d[t][1]*d[t][1];
            s1B += d[t][2] + d[t][3]; s2B += d[t][2]*d[t][2] + d[t][3]*d[t][3];
        }
        s1A = qsum(s1A); s2A = qsum(s2A); s1B = qsum(s1B); s2B = qsum(s2B);
        if (g4 == 0){
            sp[ch*128 + rowA] = make_float2(s1A, s2A);
            sp[ch*128 + rowB] = make_float2(s1B, s2B);
        }
    }
    barp(bid);                                                  // pair B3

    const float* vb = g_v + (size_t)n*16384;

    if (pad_i){
        float2 pA0 = sp[rowA], pA1 = sp[128 + rowA];
        float2 pB0 = sp[rowB], pB1 = sp[128 + rowB];
        float muA = (pA0.x + pA1.x)*(1.0f/128.0f);
        float rsA = rsqrtf((pA0.y + pA1.y)*(1.0f/128.0f) - muA*muA + 1e-5f);
        float muB = (pB0.x + pB1.x)*(1.0f/128.0f);
        float rsB = rsqrtf((pB0.y + pB1.y)*(1.0f/128.0f) - muB*muB + 1e-5f);
#pragma unroll
        for (int t = 0; t < 8; t++){
            int c0 = cb + t*8 + g4*2;
            float2 vA = *(const float2*)(vb + rowA*128 + c0);
            float2 vB = *(const float2*)(vb + rowB*128 + c0);
            sxvT[(c0  )*130 + rowA] = vA.x + fmaxf((d[t][0]-muA)*rsA, 0.0f) + rU[t][0];
            sxvT[(c0+1)*130 + rowA] = vA.y + fmaxf((d[t][1]-muA)*rsA, 0.0f) + rU[t][1];
            sxvT[(c0  )*130 + rowB] = vB.x + fmaxf((d[t][2]-muB)*rsB, 0.0f) + rU[t][2];
            sxvT[(c0+1)*130 + rowB] = vB.y + fmaxf((d[t][3]-muB)*rsB, 0.0f) + rU[t][3];
        }
        __syncthreads();
        {
            int c = tid & 127, q = tid >> 7;
            const float* row = sxvT + c*130 + q*32;
            float s = 0.0f;
#pragma unroll
            for (int j = 0; j < 32; j++) s += row[j];
            spart[c*4 + q] = s;
        }
        __syncthreads();
        if (tid < 128){
            float o = (spart[tid*4] + spart[tid*4+1] + spart[tid*4+2] + spart[tid*4+3]) * (1.0f/128.0f);
            sxo[tid] = o;
            xout[(size_t)blockIdx.x*128 + tid] = o;
        }
        __syncthreads();
        {
            int m = tid & 31, half = (tid>>5)&1, q = tid>>6;
            const float* er = e1 + m*257 + half*128 + q*16;
            const float* xo = sxo + q*16;
            float a = 0;
#pragma unroll
            for (int c2 = 0; c2 < 16; c2++) a = fmaf(xo[c2], er[c2], a);
            ((float*)(sm8 + SP2_B))[(half*32 + m)*8 + q] = a;
        }
        __syncthreads();
        if (tid < 64){
            const float* pp = (const float*)(sm8 + SP2_B);
            float a = 0;
#pragma unroll
            for (int q = 0; q < 8; q++) a += pp[tid*8 + q];
            if (tid < 32) g_avec[(size_t)blockIdx.x*32 + tid] = a;
            else          g_bvec[(size_t)blockIdx.x*32 + (tid-32)] = a;
        }
        return;
    }

    // ----- non-pad: full epi0 -----
    {
        float2 pA0 = sp[rowA], pA1 = sp[128 + rowA];
        float2 pB0 = sp[rowB], pB1 = sp[128 + rowB];
        float muA = (pA0.x + pA1.x)*(1.0f/128.0f);
        float rsA = rsqrtf((pA0.y + pA1.y)*(1.0f/128.0f) - muA*muA + 1e-5f);
        float muB = (pB0.x + pB1.x)*(1.0f/128.0f);
        float rsB = rsqrtf((pB0.y + pB1.y)*(1.0f/128.0f) - muB*muB + 1e-5f);

        const float* qb = g_q + (size_t)n*16384;
        float t1A = 0, t2A = 0, t1B = 0, t2B = 0;
#pragma unroll
        for (int t = 0; t < 8; t++){
            int c0 = cb + t*8 + g4*2;
            float2 qA = *(const float2*)(qb + rowA*128 + c0);
            float2 qB = *(const float2*)(qb + rowB*128 + c0);
            float2 vA = *(const float2*)(vb + rowA*128 + c0);
            float2 vB = *(const float2*)(vb + rowB*128 + c0);
            float2 kc = *(const float2*)(sk + c0);
            float eA0 = fmaxf((d[t][0]-muA)*rsA, 0.0f) + rU[t][0];
            float eA1 = fmaxf((d[t][1]-muA)*rsA, 0.0f) + rU[t][1];
            float eB0 = fmaxf((d[t][2]-muB)*rsB, 0.0f) + rU[t][2];
            float eB1 = fmaxf((d[t][3]-muB)*rsB, 0.0f) + rU[t][3];
            sxvT[(c0  )*130 + rowA] = vA.x + eA0;
            sxvT[(c0+1)*130 + rowA] = vA.y + eA1;
            sxvT[(c0  )*130 + rowB] = vB.x + eB0;
            sxvT[(c0+1)*130 + rowB] = vB.y + eB1;
            float rA0 = kc.x - qA.x + eA0;
            float rA1 = kc.y - qA.y + eA1;
            float rB0 = kc.x - qB.x + eB0;
            float rB1 = kc.y - qB.y + eB1;
            d[t][0] = rA0; d[t][1] = rA1; d[t][2] = rB0; d[t][3] = rB1;
            t1A += rA0 + rA1; t2A += rA0*rA0 + rA1*rA1;
            t1B += rB0 + rB1; t2B += rB0*rB0 + rB1*rB1;
        }
        t1A = qsum(t1A); t2A = qsum(t2A); t1B = qsum(t1B); t2B = qsum(t2B);
        if (g4 == 0){
            sp2[ch*128 + rowA] = make_float2(t1A, t2A);
            sp2[ch*128 + rowB] = make_float2(t1B, t2B);
        }
    }
    barp(bid);                                                  // pair B4
    {
        float2 pA0 = sp2[rowA], pA1 = sp2[128 + rowA];
        float2 pB0 = sp2[rowB], pB1 = sp2[128 + rowB];
        float nuA = (pA0.x + pA1.x)*(1.0f/128.0f);
        float nsA = rsqrtf((pA0.y + pA1.y)*(1.0f/128.0f) - nuA*nuA + 1e-5f);
        float nuB = (pB0.x + pB1.x)*(1.0f/128.0f);
        float nsB = rsqrtf((pB0.y + pB1.y)*(1.0f/128.0f) - nuB*nuB + 1e-5f);
#pragma unroll
        for (int t = 0; t < 8; t++){
            int c0 = cb + t*8 + g4*2;
            float2 gg = *(float2*)(sg1 + c0);
            float2 bb = *(float2*)(sb1v + c0);
            float yA0 = fmaxf(fmaf((d[t][0]-nuA)*nsA, gg.x, bb.x), 0.0f);
            float yA1 = fmaxf(fmaf((d[t][1]-nuA)*nsA, gg.y, bb.y), 0.0f);
            float yB0 = fmaxf(fmaf((d[t][2]-nuB)*nsB, gg.x, bb.x), 0.0f);
            float yB1 = fmaxf(fmaf((d[t][3]-nuB)*nsB, gg.y, bb.y), 0.0f);
            uint32_t hA, lA, hB, lB;
            split2(yA0, yA1, hA, lA);
            split2(yB0, yB1, hB, lB);
            int kb = cb*2 + t*16 + g4*4;
            *(uint32_t*)(sm8 + A_HI_B + swz(rowA, kb)) = hA;
            *(uint32_t*)(sm8 + A_LO_B + swz(rowA, kb)) = lA;
            *(uint32_t*)(sm8 + A_HI_B + swz(rowB, kb)) = hB;
            *(uint32_t*)(sm8 + A_LO_B + swz(rowB, kb)) = lB;
        }
    }
    barp(bid);                                                  // pair B5

    // ----- GEMM1 -----
    gemm128q(Ah, Al, Wh, Wl, r, cb, lane, d);

    // ----- epi1 -----
    {
        float s1A = 0, s2A = 0, s1B = 0, s2B = 0;
#pragma unroll
        for (int t = 0; t < 8; t++){
            int c0 = cb + t*8 + g4*2;
            float2 bb = *(float2*)(sbi1 + c0);
            d[t][0] += bb.x; d[t][1] += bb.y;
            d[t][2] += bb.x; d[t][3] += bb.y;
            s1A += d[t][0] + d[t][1]; s2A += d[t][0]*d[t][0] + d[t][1]*d[t][1];
            s1B += d[t][2] + d[t][3]; s2B += d[t][2]*d[t][2] + d[t][3]*d[t][3];
        }
        s1A = qsum(s1A); s2A = qsum(s2A); s1B = qsum(s1B); s2B = qsum(s2B);
        if (g4 == 0){
            sp[ch*128 + rowA] = make_float2(s1A, s2A);
            sp[ch*128 + rowB] = make_float2(s1B, s2B);
        }
    }
    barp(bid);                                                  // pair B6
    {
        float2 pA0 = sp[rowA], pA1 = sp[128 + rowA];
        float2 pB0 = sp[rowB], pB1 = sp[128 + rowB];
        float muA = (pA0.x + pA1.x)*(1.0f/128.0f);
        float rsA = rsqrtf((pA0.y + pA1.y)*(1.0f/128.0f) - muA*muA + 1e-5f);
        float muB = (pB0.x + pB1.x)*(1.0f/128.0f);
        float rsB = rsqrtf((pB0.y + pB1.y)*(1.0f/128.0f) - muB*muB + 1e-5f);
#pragma unroll
        for (int t = 0; t < 8; t++){
            int c0 = cb + t*8 + g4*2;
            float2 gg = *(float2*)(sg2 + c0);
            float2 bb = *(float2*)(sb2v + c0);
            float yA0 = fmaxf(fmaf((d[t][0]-muA)*rsA, gg.x, bb.x), 0.0f);
            float yA1 = fmaxf(fmaf((d[t][1]-muA)*rsA, gg.y, bb.y), 0.0f);
            float yB0 = fmaxf(fmaf((d[t][2]-muB)*rsB, gg.x, bb.x), 0.0f);
            float yB1 = fmaxf(fmaf((d[t][3]-muB)*rsB, gg.y, bb.y), 0.0f);
            uint32_t hA, lA, hB, lB;
            split2(yA0, yA1, hA, lA);
            split2(yB0, yB1, hB, lB);
            int kb = cb*2 + t*16 + g4*4;
            *(uint32_t*)(sm8 + A_HI_B + swz(rowA, kb)) = hA;
            *(uint32_t*)(sm8 + A_LO_B + swz(rowA, kb)) = lA;
            *(uint32_t*)(sm8 + A_HI_B + swz(rowB, kb)) = hB;
            *(uint32_t*)(sm8 + A_LO_B + swz(rowB, kb)) = lB;
        }
    }
    __syncthreads();                                            // FULL B7

    // ----- pair-local W2 copy -----
    {
        int pt = ch*32 + lane;
        const uint4* whi = (const uint4*)g_w2hi;
        const uint4* wlo = (const uint4*)g_w2lo;
        uint4* dhi = (uint4*)(sm8 + W_HI_B);
        uint4* dlo = (uint4*)(sm8 + W_LO_B);
#pragma unroll
        for (int t = 0; t < 4; t++){
            int idx = r*256 + pt + 64*t;
            dhi[idx] = whi[idx];
            dlo[idx] = wlo[idx];
        }
    }
    barp(bid);                                                  // pair B8

    // ----- GEMM2 transposed -----
    gemm128q(Wh, Wl, Ah, Al, r, cb, lane, d);

    // ----- softmax + weighted xv sum -----
    {
        float bA = sbi2[rowA], bB = sbi2[rowB];
        float denA = 0, numA = 0, denB = 0, numB = 0;
#pragma unroll
        for (int t = 0; t < 8; t++){
            int jj = cb + t*8 + g4*2;
            float w0 = ex2(d[t][0] + bA), w1 = ex2(d[t][1] + bA);
            float w2 = ex2(d[t][2] + bB), w3 = ex2(d[t][3] + bB);
            float2 xA = *(float2*)(sxvT + rowA*130 + jj);
            float2 xB = *(float2*)(sxvT + rowB*130 + jj);
            denA += w0 + w1; numA += w0*xA.x + w1*xA.y;
            denB += w2 + w3; numB += w2*xB.x + w3*xB.y;
        }
        denA = qsum(denA); numA = qsum(numA);
        denB = qsum(denB); numB = qsum(numB);
        if (g4 == 0){
            sdn[ch*128 + rowA] = make_float2(denA, numA);
            sdn[ch*128 + rowB] = make_float2(denB, numB);
        }
        barp(bid);                                              // pair B9
        if (ch == 0 && g4 == 0){
            float2 a0 = sdn[rowA], a1 = sdn[128 + rowA];
            float2 b0 = sdn[rowB], b1 = sdn[128 + rowB];
            float oA = (a0.y + a1.y) / (a0.x + a1.x);
            float oB = (b0.y + b1.y) / (b0.x + b1.x);
            sxo[rowA] = oA; sxo[rowB] = oB;
            xout[(size_t)blockIdx.x*128 + rowA] = oA;
            xout[(size_t)blockIdx.x*128 + rowB] = oB;
        }
    }
    __syncthreads();                                            // FULL B10

    // ----- tail -----
    {
        int m = tid & 31, half = (tid>>5)&1, q = tid>>6;
        const float* er = e1 + m*257 + half*128 + q*16;
        const float* xo = sxo + q*16;
        float a = 0;
#pragma unroll
        for (int c2 = 0; c2 < 16; c2++) a = fmaf(xo[c2], er[c2], a);
        spart[(half*32 + m)*8 + q] = a;
    }
    __syncthreads();                                            // FULL B11
    if (tid < 64){
        float a = 0;
#pragma unroll
        for (int q = 0; q < 8; q++) a += spart[tid*8 + q];
        if (tid < 32) g_avec[(size_t)blockIdx.x*32 + tid] = a;
        else          g_bvec[(size_t)blockIdx.x*32 + (tid-32)] = a;
    }
}

// ---------------- K3: message MLP + position update ----------------
__global__ void __launch_bounds__(256, 2) k3_msg(
    const float* __restrict__ p, const float* __restrict__ e1,
    const float* __restrict__ x1b, const float* __restrict__ x2,
    const float* __restrict__ x2b,
    float* __restrict__ outp)
{
    extern __shared__ char sm8[];
    float* spij  = (float*)(sm8 + K3_SPIJ);
    float* snorm = (float*)(sm8 + K3_SNORM);
    float* ss    = (float*)(sm8 + K3_SS);
    float* spad  = (float*)(sm8 + K3_SPAD);
    float* sa    = (float*)(sm8 + K3_SA);
    float* se1c  = (float*)(sm8 + K3_SE1C);
    float* sx1b_ = (float*)(sm8 + K3_SX1B);
    float* sx2v  = (float*)(sm8 + K3_SX2V);

    const uint32_t sbase = smem_u32(sm8);
    const int tid = threadIdx.x, lane = tid & 31, warp = tid >> 5;
    const int n = blockIdx.x >> 7, i = blockIdx.x & 127;
    const bool pad_i = (p[(size_t)(n*128 + i)*4] == 0.0f);

    if (pad_i){
        if (tid == 0)
            *(float4*)(outp + (size_t)(n*128 + i)*4) = make_float4(0.f, 0.f, 0.f, 0.f);
        return;
    }

    const int g4 = lane & 3;
    const int rowA = warp*16 + (lane>>2), rowB = rowA + 8;

    if (tid < 128){
        int j = tid;
        float4 pi = *(const float4*)(p + (size_t)(n*128 + i)*4);
        float4 pj = *(const float4*)(p + (size_t)(n*128 + j)*4);
        float dx = pi.x - pj.x, dy = pi.y - pj.y, dz = pi.z - pj.z, dw = pi.w - pj.w;
        spij[j*4+0] = dx; spij[j*4+1] = dy; spij[j*4+2] = dz; spij[j*4+3] = dw;
        spad[j] = (pj.x != 0.0f) ? 1.0f : 0.0f;
        snorm[j] = dw*dw - dx*dx - dy*dy - dz*dz;
    }
    if (tid < 32){
        sa[tid]    = g_avec[(size_t)(n*128 + i)*32 + tid];
        se1c[tid]  = e1[tid*257 + 256];
        sx1b_[tid] = x1b[tid];
        sx2v[tid]  = x2[tid];
    }
    {
        const uint4* e2h = (const uint4*)g_e2hi;
        const uint4* e2l = (const uint4*)g_e2lo;
        uint4* d1h = (uint4*)(sm8 + K3_B1H);
        uint4* d1l = (uint4*)(sm8 + K3_B1L);
        for (int t = tid; t < 640; t += 256){
            d1h[t] = e2h[t];
            d1l[t] = e2l[t];
        }
        const uint4* x1h = (const uint4*)g_x1hi;
        const uint4* x1l = (const uint4*)g_x1lo;
        uint4* d2h = (uint4*)(sm8 + K3_B2H);
        uint4* d2l = (uint4*)(sm8 + K3_B2L);
        for (int t = tid; t < 512; t += 256){
            d2h[t] = x1h[t];
            d2l[t] = x1l[t];
        }
    }
    __syncthreads();

    // h32 tile: warp-owned rows
    const float* bv = g_bvec + (size_t)n*4096;
#pragma unroll
    for (int rr = 0; rr < 8; rr++){
        int e = rr*32 + lane;
        int row = warp*16 + (e >> 4);
        int mp = e & 15, m = mp*2;
        float nb = snorm[row];
        float2 bb = *(const float2*)(bv + row*32 + m);
        float h0 = fmaxf(sa[m]   + bb.x + nb*se1c[m],   0.0f);
        float h1 = fmaxf(sa[m+1] + bb.y + nb*se1c[m+1], 0.0f);
        uint32_t hi, lo;
        split2(h0, h1, hi, lo);
        *(uint32_t*)(sm8 + K3_A1H + row*80 + mp*4) = hi;
        *(uint32_t*)(sm8 + K3_A1L + row*80 + mp*4) = lo;
    }
    __syncwarp();

    // MMA1
    float d[16][4];
    gemm32(sbase + K3_A1H, sbase + K3_A1L, sbase + K3_B1H, sbase + K3_B1L, warp, lane, d);

    // relu -> LN (registers)
    {
        float s1A = 0, s2A = 0, s1B = 0, s2B = 0;
#pragma unroll
        for (int t = 0; t < 16; t++){
            float a0 = fmaxf(d[t][0], 0.0f), a1 = fmaxf(d[t][1], 0.0f);
            float b0 = fmaxf(d[t][2], 0.0f), b1 = fmaxf(d[t][3], 0.0f);
            d[t][0] = a0; d[t][1] = a1; d[t][2] = b0; d[t][3] = b1;
            s1A += a0 + a1; s2A += a0*a0 + a1*a1;
            s1B += b0 + b1; s2B += b0*b0 + b1*b1;
        }
        s1A = qsum(s1A); s2A = qsum(s2A); s1B = qsum(s1B); s2B = qsum(s2B);
        float muA = s1A*(1.0f/128.0f), vA = s2A*(1.0f/128.0f) - muA*muA;
        float muB = s1B*(1.0f/128.0f), vB = s2B*(1.0f/128.0f) - muB*muB;
        float rsA = rsqrtf(fmaxf(vA, 0.0f) + 1e-5f);
        float rsB = rsqrtf(fmaxf(vB, 0.0f) + 1e-5f);
#pragma unroll
        for (int t = 0; t < 16; t++){
            d[t][0] = (d[t][0]-muA)*rsA; d[t][1] = (d[t][1]-muA)*rsA;
            d[t][2] = (d[t][2]-muB)*rsB; d[t][3] = (d[t][3]-muB)*rsB;
        }
    }

    // MMA2: A from registers
    float d2[4][4];
    mma2_regA(d, sbase + K3_B2H, sbase + K3_B2L, lane, d2);

    // scores
    {
        float x2bv = x2b[0];
        float sA = 0, sB = 0;
#pragma unroll
        for (int t = 0; t < 4; t++){
            int c0 = t*8 + g4*2;
            float2 xb = *(float2*)(sx1b_ + c0);
            float2 xv = *(float2*)(sx2v + c0);
            sA += fmaxf(d2[t][0] + xb.x, 0.0f)*xv.x + fmaxf(d2[t][1] + xb.y, 0.0f)*xv.y;
            sB += fmaxf(d2[t][2] + xb.x, 0.0f)*xv.x + fmaxf(d2[t][3] + xb.y, 0.0f)*xv.y;
        }
        sA = qsum(sA); sB = qsum(sB);
        if (g4 == 0){
            ss[rowA] = fmaxf(sA + x2bv, 0.0f);
            ss[rowB] = fmaxf(sB + x2bv, 0.0f);
        }
    }
    __syncthreads();

    if (warp == 0){
        float m0 = fmaxf(fmaxf(ss[lane], ss[lane+32]), fmaxf(ss[lane+64], ss[lane+96]));
#pragma unroll
        for (int k = 16; k > 0; k >>= 1) m0 = fmaxf(m0, __shfl_xor_sync(0xffffffffu, m0, k));
        float den = 0, dx = 0, dy = 0, dz = 0, dw = 0, cnt = 0;
#pragma unroll
        for (int q2 = 0; q2 < 4; q2++){
            int b = lane + 32*q2;
            float w = __expf(ss[b] - m0);
            den += w;
            dx = fmaf(w, spij[b*4+0], dx);
            dy = fmaf(w, spij[b*4+1], dy);
            dz = fmaf(w, spij[b*4+2], dz);
            dw = fmaf(w, spij[b*4+3], dw);
            cnt += spad[b];
        }
        den = wsum(den); dx = wsum(dx); dy = wsum(dy);
        dz = wsum(dz);   dw = wsum(dw); cnt = wsum(cnt);
        if (lane == 0){
            float inv = 1.0f / (den * cnt);
            const float* pr = p + (size_t)(n*128 + i)*4;
            float* o = outp + (size_t)(n*128 + i)*4;
            float d4[4] = {dx, dy, dz, dw};
#pragma unroll
            for (int dd = 0; dd < 4; dd++){
                float pv = pr[dd];
                o[dd] = (pv == 0.0f) ? 0.0f : pv + d4[dd]*inv;
            }
        }
    }
}

extern "C" void kernel_launch(void* const* d_in, const int* in_sizes, int n_in,
                              void* d_out, int out_size){
    const float* x     = (const float*)d_in[0];
    const float* p     = (const float*)d_in[1];
    const float* U     = (const float*)d_in[2];
    const float* wq    = (const float*)d_in[3];
    const float* bq    = (const float*)d_in[4];
    const float* wk    = (const float*)d_in[5];
    const float* bk    = (const float*)d_in[6];
    const float* wv    = (const float*)d_in[7];
    const float* bv    = (const float*)d_in[8];
    const float* ln1_g = (const float*)d_in[9];
    const float* ln1_b = (const float*)d_in[10];
    const float* w1    = (const float*)d_in[11];
    const float* b1    = (const float*)d_in[12];
    const float* ln2_g = (const float*)d_in[13];
    const float* ln2_b = (const float*)d_in[14];
    const float* w2    = (const float*)d_in[15];
    const float* b2    = (const float*)d_in[16];
    const float* pe1   = (const float*)d_in[17];
    const float* pe2   = (const float*)d_in[18];
    const float* e1    = (const float*)d_in[19];
    const float* e2    = (const float*)d_in[20];
    const float* x1    = (const float*)d_in[21];
    const float* x1b   = (const float*)d_in[22];
    const float* x2    = (const float*)d_in[23];
    const float* x2b   = (const float*)d_in[24];
    float* out  = (float*)d_out;
    float* xout = out;
    float* newp = out + 16*128*128;

    cudaFuncSetAttribute(k2_attn, cudaFuncAttributeMaxDynamicSharedMemorySize, K2_SMEM);
    cudaFuncSetAttribute(k3_msg,  cudaFuncAttributeMaxDynamicSharedMemorySize, K3_SMEM);

    k0_prep<<<64, 256>>>(wq, wk, wv, w1, w2, pe2, e2, x1);
    k1_qkv<<<2048, 128>>>(x, bq, bk, bv);
    k2_attn<<<2048, 512, K2_SMEM>>>(U, p, ln1_g, ln1_b, b1, ln2_g, ln2_b, b2, pe1, e1, xout);
    k3_msg<<<2048, 256, K3_SMEM>>>(p, e1, x1b, x2, x2b, newp);
}

// round 14
// speedup vs baseline: 1.0328x; 1.0328x over previous
#include <cuda_runtime.h>
#include <cuda_bf16.h>
#include <math.h>
#include <stdint.h>

#define NEGV (-10000.0f)
#define LOG2E 1.44269504088896340736f

// ---------------- K2 smem byte offsets ----------------
#define XVT_B    0
#define PE2H_B   0
#define PE2L_B   10240
#define TNH_B    20480
#define TNL_B    30720
#define A_HI_B   67584
#define A_LO_B   100352
#define W_HI_B   133120
#define W_LO_B   165888
#define SK_B     198656
#define SG1_B    199168
#define SB1_B    199680
#define SG2_B    200192
#define SB2_B    200704
#define SBI1_B   201216
#define SBI2_B   201728
#define SPE1_B   202240
#define SPIJ_B   202752
#define SXO_B    204800
#define SP_B     205312
#define SP2_B    207360
#define SDN_B    209408
#define K2_SMEM  211456

// xvT row stride in floats (conflict-free stores: 132*2 mod 32 banks = 8 per g4)
#define XVS 132

// ---------------- K3 smem byte offsets ----------------
#define K3_A1H   0
#define K3_A1L   10240
#define K3_B1H   20480
#define K3_B1L   30720
#define K3_B2H   40960
#define K3_B2L   49152
#define K3_SPIJ  57344
#define K3_SNORM 59392
#define K3_SS    59904
#define K3_SPAD  60416
#define K3_SA    60928
#define K3_SE1C  61056
#define K3_SX1B  61184
#define K3_SX2V  61312
#define K3_SMEM  61440

// ---------------- device scratch ----------------
__device__ float g_q[16*128*128];
__device__ float g_k[16*128*128];
__device__ float g_v[16*128*128];
__device__ float g_wqT[64*128];
__device__ float g_wkT[64*128];
__device__ float g_wvT[64*128];
__device__ float g_avec[16*128*32];
__device__ float g_bvec[16*128*32];
__device__ uint32_t g_w1hi[8192];
__device__ uint32_t g_w1lo[8192];
__device__ uint32_t g_w2hi[8192];
__device__ uint32_t g_w2lo[8192];
__device__ uint32_t g_x1hi[2048];
__device__ uint32_t g_x1lo[2048];
__device__ uint32_t g_pe2hi[2560];
__device__ uint32_t g_pe2lo[2560];
__device__ uint32_t g_e2hi[2560];
__device__ uint32_t g_e2lo[2560];

// ---------------- helpers ----------------
__device__ __forceinline__ float wsum(float v){
#pragma unroll
    for (int k = 16; k > 0; k >>= 1) v += __shfl_xor_sync(0xffffffffu, v, k);
    return v;
}
__device__ __forceinline__ float qsum(float v){
    v += __shfl_xor_sync(0xffffffffu, v, 1);
    v += __shfl_xor_sync(0xffffffffu, v, 2);
    return v;
}
__device__ __forceinline__ uint32_t smem_u32(const void* p){
    uint32_t a;
    asm("{ .reg .u64 t; cvta.to.shared.u64 t, %1; cvt.u32.u64 %0, t; }" : "=r"(a) : "l"(p));
    return a;
}
__device__ __forceinline__ uint32_t swz(int row, int kb){
    return (uint32_t)(row*256 + ((kb & 0xF0) ^ ((row & 7) << 4)) + (kb & 15));
}
__device__ __forceinline__ float ex2(float x){
    float r; asm("ex2.approx.ftz.f32 %0, %1;" : "=f"(r) : "f"(x)); return r;
}
__device__ __forceinline__ void barp(int id){
    asm volatile("bar.sync %0, 64;" :: "r"(id) : "memory");
}
__device__ __forceinline__ void split2(float x, float y, uint32_t &hi, uint32_t &lo){
    uint32_t h;
    asm("cvt.rn.bf16x2.f32 %0, %1, %2;" : "=r"(h) : "f"(y), "f"(x));
    float xh = __uint_as_float(h << 16);
    float yh = __uint_as_float(h & 0xFFFF0000u);
    asm("cvt.rn.bf16x2.f32 %0, %1, %2;" : "=r"(lo) : "f"(y - yh), "f"(x - xh));
    hi = h;
}
__device__ __forceinline__ void ldsm4(uint32_t a[4], uint32_t addr){
    asm volatile("ldmatrix.sync.aligned.m8n8.x4.shared.b16 {%0,%1,%2,%3}, [%4];"
        : "=r"(a[0]), "=r"(a[1]), "=r"(a[2]), "=r"(a[3]) : "r"(addr));
}
__device__ __forceinline__ void mma16816(float d[4], const uint32_t a[4], const uint32_t b[2]){
    asm volatile("mma.sync.aligned.m16n8k16.row.col.f32.bf16.bf16.f32 "
        "{%0,%1,%2,%3}, {%4,%5,%6,%7}, {%8,%9}, {%0,%1,%2,%3};"
        : "+f"(d[0]), "+f"(d[1]), "+f"(d[2]), "+f"(d[3])
        : "r"(a[0]), "r"(a[1]), "r"(a[2]), "r"(a[3]), "r"(b[0]), "r"(b[1]));
}

// K2 quadrant GEMM (r12 form — measured best; do not touch)
__device__ __forceinline__ void gemm128q(uint32_t Ah, uint32_t Al, uint32_t Bh, uint32_t Bl,
                                         int r, int cb, int lane, float d[8][4]){
#pragma unroll
    for (int t = 0; t < 8; t++){ d[t][0]=0.f; d[t][1]=0.f; d[t][2]=0.f; d[t][3]=0.f; }
    const uint32_t aro = (uint32_t)((r*16 + (lane&15))*256);
    const uint32_t aox = (uint32_t)((lane&7)<<4);
    const uint32_t akx = (uint32_t)(lane&16);
    const uint32_t bro = (uint32_t)((cb + (lane&7) + ((lane>>4)<<3))*256);
    const uint32_t bkx = (uint32_t)((lane&8)<<1);
#pragma unroll 1
    for (int kk = 0; kk < 8; kk++){
        uint32_t ka = (uint32_t)(kk*32);
        uint32_t ah[4], al_[4];
        ldsm4(ah,  Ah + aro + ((ka + akx) ^ aox));
        ldsm4(al_, Al + aro + ((ka + akx) ^ aox));
        uint32_t bo = bro + ((ka + bkx) ^ aox);
#pragma unroll
        for (int t2 = 0; t2 < 4; t2++){
            uint32_t bh[4], bl[4];
            ldsm4(bh, Bh + bo + (uint32_t)(t2*4096));
            ldsm4(bl, Bl + bo + (uint32_t)(t2*4096));
            mma16816(d[2*t2],   ah,  bh);
            mma16816(d[2*t2+1], ah,  bh+2);
            mma16816(d[2*t2],   ah,  bl);
            mma16816(d[2*t2+1], ah,  bl+2);
            mma16816(d[2*t2],   al_, bh);
            mma16816(d[2*t2+1], al_, bh+2);
        }
    }
}

// K2 quadrant small-K GEMM: K=32, 80B-stride tiles.
__device__ __forceinline__ void gemm32q(uint32_t Ah, uint32_t Al, uint32_t Bh, uint32_t Bl,
                                        int r, int cb, int lane, float d[8][4]){
#pragma unroll
    for (int t = 0; t < 8; t++){ d[t][0]=0.f; d[t][1]=0.f; d[t][2]=0.f; d[t][3]=0.f; }
    const uint32_t aro = (uint32_t)((r*16 + (lane&15))*80 + (lane&16));
    const uint32_t bro = (uint32_t)((cb + (lane&7) + ((lane>>4)<<3))*80 + ((lane&8)<<1));
#pragma unroll
    for (int kk = 0; kk < 2; kk++){
        uint32_t ah[4], al_[4];
        ldsm4(ah,  Ah + aro + (uint32_t)(kk*32));
        ldsm4(al_, Al + aro + (uint32_t)(kk*32));
#pragma unroll
        for (int t2 = 0; t2 < 4; t2++){
            uint32_t bh[4], bl[4];
            ldsm4(bh, Bh + bro + (uint32_t)(kk*32 + t2*1280));
            ldsm4(bl, Bl + bro + (uint32_t)(kk*32 + t2*1280));
            mma16816(d[2*t2],   ah,  bh);
            mma16816(d[2*t2+1], ah,  bh+2);
            mma16816(d[2*t2],   ah,  bl);
            mma16816(d[2*t2+1], ah,  bl+2);
            mma16816(d[2*t2],   al_, bh);
            mma16816(d[2*t2+1], al_, bh+2);
        }
    }
}

// K3 full-width K=32 GEMM
__device__ __forceinline__ void gemm32(uint32_t Ah, uint32_t Al, uint32_t Bh, uint32_t Bl,
                                       int warp, int lane, float d[16][4]){
#pragma unroll
    for (int t = 0; t < 16; t++){ d[t][0]=0.f; d[t][1]=0.f; d[t][2]=0.f; d[t][3]=0.f; }
    const uint32_t aro = (uint32_t)((warp*16 + (lane&15))*80 + (lane&16));
    const uint32_t bro = (uint32_t)(((lane&7) + ((lane>>4)<<3))*80 + ((lane&8)<<1));
#pragma unroll
    for (int kk = 0; kk < 2; kk++){
        uint32_t ah[4], al_[4];
        ldsm4(ah,  Ah + aro + (uint32_t)(kk*32));
        ldsm4(al_, Al + aro + (uint32_t)(kk*32));
#pragma unroll
        for (int t2 = 0; t2 < 8; t2++){
            uint32_t bh[4], bl[4];
            ldsm4(bh, Bh + bro + (uint32_t)(kk*32 + t2*1280));
            ldsm4(bl, Bl + bro + (uint32_t)(kk*32 + t2*1280));
            mma16816(d[2*t2],   ah,  bh);
            mma16816(d[2*t2+1], ah,  bh+2);
            mma16816(d[2*t2],   ah,  bl);
            mma16816(d[2*t2+1], ah,  bl+2);
            mma16816(d[2*t2],   al_, bh);
            mma16816(d[2*t2+1], al_, bh+2);
        }
    }
}

// K3 MMA2 with A from registers
__device__ __forceinline__ void mma2_regA(const float y[16][4], uint32_t Bh, uint32_t Bl,
                                          int lane, float d2[4][4]){
#pragma unroll
    for (int t = 0; t < 4; t++){ d2[t][0]=0.f; d2[t][1]=0.f; d2[t][2]=0.f; d2[t][3]=0.f; }
    const uint32_t aox = (uint32_t)((lane&7)<<4);
    const uint32_t bro = (uint32_t)(((lane&7) + ((lane>>4)<<3))*256);
    const uint32_t bkx = (uint32_t)((lane&8)<<1);
#pragma unroll
    for (int kt = 0; kt < 8; kt++){
        uint32_t ah[4], al_[4];
        split2(y[2*kt][0],   y[2*kt][1],   ah[0], al_[0]);
        split2(y[2*kt][2],   y[2*kt][3],   ah[1], al_[1]);
        split2(y[2*kt+1][0], y[2*kt+1][1], ah[2], al_[2]);
        split2(y[2*kt+1][2], y[2*kt+1][3], ah[3], al_[3]);
        uint32_t bo = bro + (((uint32_t)(kt*32) + bkx) ^ aox);
#pragma unroll
        for (int t2 = 0; t2 < 2; t2++){
            uint32_t bh[4], bl[4];
            ldsm4(bh, Bh + bo + (uint32_t)(t2*4096));
            ldsm4(bl, Bl + bo + (uint32_t)(t2*4096));
            mma16816(d2[2*t2],   ah,  bh);
            mma16816(d2[2*t2+1], ah,  bh+2);
            mma16816(d2[2*t2],   ah,  bl);
            mma16816(d2[2*t2+1], ah,  bl+2);
            mma16816(d2[2*t2],   al_, bh);
            mma16816(d2[2*t2+1], al_, bh+2);
        }
    }
}

// ---------------- K0: weight prep ----------------
__global__ void k0_prep(const float* __restrict__ wq, const float* __restrict__ wk,
                        const float* __restrict__ wv, const float* __restrict__ w1,
                        const float* __restrict__ w2, const float* __restrict__ pe2,
                        const float* __restrict__ e2, const float* __restrict__ x1){
    int idx = blockIdx.x * blockDim.x + threadIdx.x;
    int stride = gridDim.x * blockDim.x;
    for (int t = idx; t < 16384; t += stride){
        int c = t >> 7, m = t & 127;
        uint32_t a = swz(c, m*2) >> 1;
        float v1 = w1[t];
        __nv_bfloat16 h1 = __float2bfloat16(v1);
        ((unsigned short*)g_w1hi)[a] = __bfloat16_as_ushort(h1);
        ((unsigned short*)g_w1lo)[a] = __bfloat16_as_ushort(__float2bfloat16(v1 - __bfloat162float(h1)));
        float v2 = w2[t] * LOG2E;
        __nv_bfloat16 h2 = __float2bfloat16(v2);
        ((unsigned short*)g_w2hi)[a] = __bfloat16_as_ushort(h2);
        ((unsigned short*)g_w2lo)[a] = __bfloat16_as_ushort(__float2bfloat16(v2 - __bfloat162float(h2)));
    }
    for (int t = idx; t < 4096; t += stride){
        int c = t >> 5, m = t & 31;
        uint32_t a80 = (uint32_t)(c*40 + m);
        float vp = pe2[t];
        __nv_bfloat16 hp = __float2bfloat16(vp);
        ((unsigned short*)g_pe2hi)[a80] = __bfloat16_as_ushort(hp);
        ((unsigned short*)g_pe2lo)[a80] = __bfloat16_as_ushort(__float2bfloat16(vp - __bfloat162float(hp)));
        float ve = e2[t];
        __nv_bfloat16 he = __float2bfloat16(ve);
        ((unsigned short*)g_e2hi)[a80] = __bfloat16_as_ushort(he);
        ((unsigned short*)g_e2lo)[a80] = __bfloat16_as_ushort(__float2bfloat16(ve - __bfloat162float(he)));
        int m2 = t >> 7, c2 = t & 127;
        uint32_t ax = swz(m2, c2*2) >> 1;
        float vx = x1[t];
        __nv_bfloat16 hx = __float2bfloat16(vx);
        ((unsigned short*)g_x1hi)[ax] = __bfloat16_as_ushort(hx);
        ((unsigned short*)g_x1lo)[ax] = __bfloat16_as_ushort(__float2bfloat16(vx - __bfloat162float(hx)));
    }
    for (int t = idx; t < 8192; t += stride){
        int c = t >> 6, d = t & 63;
        g_wqT[d*128 + c] = wq[t];
        g_wkT[d*128 + c] = wk[t];
        g_wvT[d*128 + c] = wv[t];
    }
}

// ---------------- K1: q,k,v projections ----------------
__global__ void __launch_bounds__(128) k1_qkv(const float* __restrict__ x,
                                              const float* __restrict__ bq,
                                              const float* __restrict__ bk,
                                              const float* __restrict__ bv){
    __shared__ float sx[64];
    int row = blockIdx.x;
    int c = threadIdx.x;
    if (c < 64) sx[c] = x[(size_t)row*64 + c];
    __syncthreads();
    float aq = bq[c], ak = bk[c], av = bv[c];
#pragma unroll 8
    for (int d = 0; d < 64; d++){
        float xv = sx[d];
        aq = fmaf(xv, g_wqT[d*128 + c], aq);
        ak = fmaf(xv, g_wkT[d*128 + c], ak);
        av = fmaf(xv, g_wvT[d*128 + c], av);
    }
    g_q[(size_t)row*128 + c] = aq;
    g_k[(size_t)row*128 + c] = ak;
    g_v[(size_t)row*128 + c] = av;
}

// ---------------- K2: fused attention per (n,i) ----------------
__global__ void __launch_bounds__(512) k2_attn(
    const float* __restrict__ U, const float* __restrict__ p,
    const float* __restrict__ ln1_g, const float* __restrict__ ln1_b,
    const float* __restrict__ b1,
    const float* __restrict__ ln2_g, const float* __restrict__ ln2_b,
    const float* __restrict__ b2,
    const float* __restrict__ pe1, const float* __restrict__ e1,
    float* __restrict__ xout)
{
    extern __shared__ char sm8[];
    float*  sxvT = (float*)(sm8 + XVT_B);     // [c][j] stride XVS=132
    float*  sk   = (float*)(sm8 + SK_B);
    float*  sg1  = (float*)(sm8 + SG1_B);
    float*  sb1v = (float*)(sm8 + SB1_B);
    float*  sg2  = (float*)(sm8 + SG2_B);
    float*  sb2v = (float*)(sm8 + SB2_B);
    float*  sbi1 = (float*)(sm8 + SBI1_B);
    float*  sbi2 = (float*)(sm8 + SBI2_B);
    float*  spe1 = (float*)(sm8 + SPE1_B);
    float*  spij = (float*)(sm8 + SPIJ_B);
    float*  sxo  = (float*)(sm8 + SXO_B);
    float2* sp   = (float2*)(sm8 + SP_B);
    float*  spart= (float*)(sm8 + SP_B);
    float2* sp2  = (float2*)(sm8 + SP2_B);
    float2* sdn  = (float2*)(sm8 + SDN_B);

    const uint32_t sbase = smem_u32(sm8);
    const uint32_t Ah = sbase + A_HI_B, Al = sbase + A_LO_B;
    const uint32_t Wh = sbase + W_HI_B, Wl = sbase + W_LO_B;
    const int tid = threadIdx.x;
    const int lane = tid & 31, warp = tid >> 5;
    const int r = warp & 7, ch = warp >> 3;
    const int cb = ch*64;
    const int bid = r + 1;
    const int n = blockIdx.x >> 7, i = blockIdx.x & 127;
    const int g4 = lane & 3;
    const int rowA = r*16 + (lane>>2), rowB = rowA + 8;

    const float* Ub = U + (size_t)blockIdx.x * 16384;
    asm volatile("prefetch.global.L2 [%0];" :: "l"(Ub + (tid << 5)));

    // ----- stage 0 -----
    if (tid < 128){
        size_t rowk = (size_t)(n*128 + i);
        sk[tid]   = g_k[rowk*128 + tid];
        sg1[tid]  = ln1_g[tid];  sb1v[tid] = ln1_b[tid];
        sg2[tid]  = ln2_g[tid];  sb2v[tid] = ln2_b[tid];
        sbi1[tid] = b1[tid];     sbi2[tid] = b2[tid] * LOG2E;
        spe1[tid] = pe1[tid];
        int j = tid;
        float4 pi = *(const float4*)(p + (size_t)(n*128 + i)*4);
        float4 pj = *(const float4*)(p + (size_t)(n*128 + j)*4);
        spij[j*4+0] = pi.x - pj.x;
        spij[j*4+1] = pi.y - pj.y;
        spij[j*4+2] = pi.z - pj.z;
        spij[j*4+3] = pi.w - pj.w;
    }
    for (int t = tid; t < 2560; t += 512){
        ((uint32_t*)(sm8 + PE2H_B))[t] = g_pe2hi[t];
        ((uint32_t*)(sm8 + PE2L_B))[t] = g_pe2lo[t];
    }
    {
        const uint4* whi = (const uint4*)g_w1hi;
        const uint4* wlo = (const uint4*)g_w1lo;
        uint4* dhi = (uint4*)(sm8 + W_HI_B);
        uint4* dlo = (uint4*)(sm8 + W_LO_B);
#pragma unroll
        for (int t = 0; t < 4; t++){
            dhi[tid + 512*t] = whi[tid + 512*t];
            dlo[tid + 512*t] = wlo[tid + 512*t];
        }
    }
    const bool pad_i = (p[(size_t)(n*128 + i)*4] == 0.0f);
    __syncthreads();                                            // FULL B1

    // ----- U register prefetch -----
    float rU[8][4];
#pragma unroll
    for (int t = 0; t < 8; t++){
        int c0 = cb + t*8 + g4*2;
        float2 uA = *(const float2*)(Ub + rowA*128 + c0);
        float2 uB = *(const float2*)(Ub + rowB*128 + c0);
        rU[t][0] = uA.x; rU[t][1] = uA.y;
        rU[t][2] = uB.x; rU[t][3] = uB.y;
    }

    // ----- tn: pair-owned rows -----
    {
        float4 pe1r = ((const float4*)spe1)[lane];
#pragma unroll 1
        for (int rr = 0; rr < 8; rr++){
            int jj = r*16 + ch*8 + rr;
            float4 pd = *(const float4*)(spij + jj*4);
            float t = pd.x*pe1r.x + pd.y*pe1r.y + pd.z*pe1r.z + pd.w*pe1r.w;
            float s1 = t, s2v = t*t;
#pragma unroll
            for (int k = 16; k > 0; k >>= 1){
                s1  += __shfl_xor_sync(0xffffffffu, s1,  k);
                s2v += __shfl_xor_sync(0xffffffffu, s2v, k);
            }
            float mu = s1 * (1.0f/32.0f);
            float var = fmaxf(s2v*(1.0f/32.0f) - mu*mu, 0.0f);
            float tn = fmaxf((t - mu) * rsqrtf(var + 1e-5f), 0.0f);
            float tn1 = __shfl_down_sync(0xffffffffu, tn, 1);
            if (!(lane & 1)){
                uint32_t hi, lo;
                split2(tn, tn1, hi, lo);
                *(uint32_t*)(sm8 + TNH_B + jj*80 + lane*2) = hi;
                *(uint32_t*)(sm8 + TNL_B + jj*80 + lane*2) = lo;
            }
        }
    }
    barp(bid);                                                  // pair B2

    // ----- GEMM0 -----
    float d[8][4];
    gemm32q(sbase + TNH_B, sbase + TNL_B, sbase + PE2H_B, sbase + PE2L_B, r, cb, lane, d);

    // ----- epi0 stats -----
    {
        float s1A = 0, s2A = 0, s1B = 0, s2B = 0;
#pragma unroll
        for (int t = 0; t < 8; t++){
            s1A += d[t][0] + d[t][1]; s2A += d[t][0]*d[t][0] + d[t][1]*d[t][1];
            s1B += d[t][2] + d[t][3]; s2B += d[t][2]*d[t][2] + d[t][3]*d[t][3];
        }
        s1A = qsum(s1A); s2A = qsum(s2A); s1B = qsum(s1B); s2B = qsum(s2B);
        if (g4 == 0){
            sp[ch*128 + rowA] = make_float2(s1A, s2A);
            sp[ch*128 + rowB] = make_float2(s1B, s2B);
        }
    }
    barp(bid);                                                  // pair B3

    const float* vb = g_v + (size_t)n*16384;

    if (pad_i){
        float2 pA0 = sp[rowA], pA1 = sp[128 + rowA];
        float2 pB0 = sp[rowB], pB1 = sp[128 + rowB];
        float muA = (pA0.x + pA1.x)*(1.0f/128.0f);
        float rsA = rsqrtf((pA0.y + pA1.y)*(1.0f/128.0f) - muA*muA + 1e-5f);
        float muB = (pB0.x + pB1.x)*(1.0f/128.0f);
        float rsB = rsqrtf((pB0.y + pB1.y)*(1.0f/128.0f) - muB*muB + 1e-5f);
#pragma unroll
        for (int t = 0; t < 8; t++){
            int c0 = cb + t*8 + g4*2;
            float2 vA = *(const float2*)(vb + rowA*128 + c0);
            float2 vB = *(const float2*)(vb + rowB*128 + c0);
            sxvT[(c0  )*XVS + rowA] = vA.x + fmaxf((d[t][0]-muA)*rsA, 0.0f) + rU[t][0];
            sxvT[(c0+1)*XVS + rowA] = vA.y + fmaxf((d[t][1]-muA)*rsA, 0.0f) + rU[t][1];
            sxvT[(c0  )*XVS + rowB] = vB.x + fmaxf((d[t][2]-muB)*rsB, 0.0f) + rU[t][2];
            sxvT[(c0+1)*XVS + rowB] = vB.y + fmaxf((d[t][3]-muB)*rsB, 0.0f) + rU[t][3];
        }
        __syncthreads();
        {
            int c = tid & 127, q = tid >> 7;
            const float* row = sxvT + c*XVS + q*32;
            float s = 0.0f;
#pragma unroll
            for (int j = 0; j < 32; j++) s += row[j];
            spart[c*4 + q] = s;
        }
        __syncthreads();
        if (tid < 128){
            float o = (spart[tid*4] + spart[tid*4+1] + spart[tid*4+2] + spart[tid*4+3]) * (1.0f/128.0f);
            sxo[tid] = o;
            xout[(size_t)blockIdx.x*128 + tid] = o;
        }
        __syncthreads();
        {
            int m = tid & 31, half = (tid>>5)&1, q = tid>>6;
            const float* er = e1 + m*257 + half*128 + q*16;
            const float* xo = sxo + q*16;
            float a = 0;
#pragma unroll
            for (int c2 = 0; c2 < 16; c2++) a = fmaf(xo[c2], er[c2], a);
            ((float*)(sm8 + SP2_B))[(half*32 + m)*8 + q] = a;
        }
        __syncthreads();
        if (tid < 64){
            const float* pp = (const float*)(sm8 + SP2_B);
            float a = 0;
#pragma unroll
            for (int q = 0; q < 8; q++) a += pp[tid*8 + q];
            if (tid < 32) g_avec[(size_t)blockIdx.x*32 + tid] = a;
            else          g_bvec[(size_t)blockIdx.x*32 + (tid-32)] = a;
        }
        return;
    }

    // ----- non-pad: full epi0 -----
    {
        float2 pA0 = sp[rowA], pA1 = sp[128 + rowA];
        float2 pB0 = sp[rowB], pB1 = sp[128 + rowB];
        float muA = (pA0.x + pA1.x)*(1.0f/128.0f);
        float rsA = rsqrtf((pA0.y + pA1.y)*(1.0f/128.0f) - muA*muA + 1e-5f);
        float muB = (pB0.x + pB1.x)*(1.0f/128.0f);
        float rsB = rsqrtf((pB0.y + pB1.y)*(1.0f/128.0f) - muB*muB + 1e-5f);

        const float* qb = g_q + (size_t)n*16384;
        float t1A = 0, t2A = 0, t1B = 0, t2B = 0;
#pragma unroll
        for (int t = 0; t < 8; t++){
            int c0 = cb + t*8 + g4*2;
            float2 qA = *(const float2*)(qb + rowA*128 + c0);
            float2 qB = *(const float2*)(qb + rowB*128 + c0);
            float2 vA = *(const float2*)(vb + rowA*128 + c0);
            float2 vB = *(const float2*)(vb + rowB*128 + c0);
            float2 kc = *(const float2*)(sk + c0);
            float eA0 = fmaxf((d[t][0]-muA)*rsA, 0.0f) + rU[t][0];
            float eA1 = fmaxf((d[t][1]-muA)*rsA, 0.0f) + rU[t][1];
            float eB0 = fmaxf((d[t][2]-muB)*rsB, 0.0f) + rU[t][2];
            float eB1 = fmaxf((d[t][3]-muB)*rsB, 0.0f) + rU[t][3];
            sxvT[(c0  )*XVS + rowA] = vA.x + eA0;
            sxvT[(c0+1)*XVS + rowA] = vA.y + eA1;
            sxvT[(c0  )*XVS + rowB] = vB.x + eB0;
            sxvT[(c0+1)*XVS + rowB] = vB.y + eB1;
            float rA0 = kc.x - qA.x + eA0;
            float rA1 = kc.y - qA.y + eA1;
            float rB0 = kc.x - qB.x + eB0;
            float rB1 = kc.y - qB.y + eB1;
            d[t][0] = rA0; d[t][1] = rA1; d[t][2] = rB0; d[t][3] = rB1;
            t1A += rA0 + rA1; t2A += rA0*rA0 + rA1*rA1;
            t1B += rB0 + rB1; t2B += rB0*rB0 + rB1*rB1;
        }
        t1A = qsum(t1A); t2A = qsum(t2A); t1B = qsum(t1B); t2B = qsum(t2B);
        if (g4 == 0){
            sp2[ch*128 + rowA] = make_float2(t1A, t2A);
            sp2[ch*128 + rowB] = make_float2(t1B, t2B);
        }
    }
    barp(bid);                                                  // pair B4
    {
        float2 pA0 = sp2[rowA], pA1 = sp2[128 + rowA];
        float2 pB0 = sp2[rowB], pB1 = sp2[128 + rowB];
        float nuA = (pA0.x + pA1.x)*(1.0f/128.0f);
        float nsA = rsqrtf((pA0.y + pA1.y)*(1.0f/128.0f) - nuA*nuA + 1e-5f);
        float nuB = (pB0.x + pB1.x)*(1.0f/128.0f);
        float nsB = rsqrtf((pB0.y + pB1.y)*(1.0f/128.0f) - nuB*nuB + 1e-5f);
#pragma unroll
        for (int t = 0; t < 8; t++){
            int c0 = cb + t*8 + g4*2;
            float2 gg = *(float2*)(sg1 + c0);
            float2 bb = *(float2*)(sb1v + c0);
            float yA0 = fmaxf(fmaf((d[t][0]-nuA)*nsA, gg.x, bb.x), 0.0f);
            float yA1 = fmaxf(fmaf((d[t][1]-nuA)*nsA, gg.y, bb.y), 0.0f);
            float yB0 = fmaxf(fmaf((d[t][2]-nuB)*nsB, gg.x, bb.x), 0.0f);
            float yB1 = fmaxf(fmaf((d[t][3]-nuB)*nsB, gg.y, bb.y), 0.0f);
            uint32_t hA, lA, hB, lB;
            split2(yA0, yA1, hA, lA);
            split2(yB0, yB1, hB, lB);
            int kb = cb*2 + t*16 + g4*4;
            *(uint32_t*)(sm8 + A_HI_B + swz(rowA, kb)) = hA;
            *(uint32_t*)(sm8 + A_LO_B + swz(rowA, kb)) = lA;
            *(uint32_t*)(sm8 + A_HI_B + swz(rowB, kb)) = hB;
            *(uint32_t*)(sm8 + A_LO_B + swz(rowB, kb)) = lB;
        }
    }
    barp(bid);                                                  // pair B5

    // ----- GEMM1 -----
    gemm128q(Ah, Al, Wh, Wl, r, cb, lane, d);

    // ----- epi1 -----
    {
        float s1A = 0, s2A = 0, s1B = 0, s2B = 0;
#pragma unroll
        for (int t = 0; t < 8; t++){
            int c0 = cb + t*8 + g4*2;
            float2 bb = *(float2*)(sbi1 + c0);
            d[t][0] += bb.x; d[t][1] += bb.y;
            d[t][2] += bb.x; d[t][3] += bb.y;
            s1A += d[t][0] + d[t][1]; s2A += d[t][0]*d[t][0] + d[t][1]*d[t][1];
            s1B += d[t][2] + d[t][3]; s2B += d[t][2]*d[t][2] + d[t][3]*d[t][3];
        }
        s1A = qsum(s1A); s2A = qsum(s2A); s1B = qsum(s1B); s2B = qsum(s2B);
        if (g4 == 0){
            sp[ch*128 + rowA] = make_float2(s1A, s2A);
            sp[ch*128 + rowB] = make_float2(s1B, s2B);
        }
    }
    barp(bid);                                                  // pair B6
    {
        float2 pA0 = sp[rowA], pA1 = sp[128 + rowA];
        float2 pB0 = sp[rowB], pB1 = sp[128 + rowB];
        float muA = (pA0.x + pA1.x)*(1.0f/128.0f);
        float rsA = rsqrtf((pA0.y + pA1.y)*(1.0f/128.0f) - muA*muA + 1e-5f);
        float muB = (pB0.x + pB1.x)*(1.0f/128.0f);
        float rsB = rsqrtf((pB0.y + pB1.y)*(1.0f/128.0f) - muB*muB + 1e-5f);
#pragma unroll
        for (int t = 0; t < 8; t++){
            int c0 = cb + t*8 + g4*2;
            float2 gg = *(float2*)(sg2 + c0);
            float2 bb = *(float2*)(sb2v + c0);
            float yA0 = fmaxf(fmaf((d[t][0]-muA)*rsA, gg.x, bb.x), 0.0f);
            float yA1 = fmaxf(fmaf((d[t][1]-muA)*rsA, gg.y, bb.y), 0.0f);
            float yB0 = fmaxf(fmaf((d[t][2]-muB)*rsB, gg.x, bb.x), 0.0f);
            float yB1 = fmaxf(fmaf((d[t][3]-muB)*rsB, gg.y, bb.y), 0.0f);
            uint32_t hA, lA, hB, lB;
            split2(yA0, yA1, hA, lA);
            split2(yB0, yB1, hB, lB);
            int kb = cb*2 + t*16 + g4*4;
            *(uint32_t*)(sm8 + A_HI_B + swz(rowA, kb)) = hA;
            *(uint32_t*)(sm8 + A_LO_B + swz(rowA, kb)) = lA;
            *(uint32_t*)(sm8 + A_HI_B + swz(rowB, kb)) = hB;
            *(uint32_t*)(sm8 + A_LO_B + swz(rowB, kb)) = lB;
        }
    }
    __syncthreads();                                            // FULL B7

    // ----- pair-local W2 copy -----
    {
        int pt = ch*32 + lane;
        const uint4* whi = (const uint4*)g_w2hi;
        const uint4* wlo = (const uint4*)g_w2lo;
        uint4* dhi = (uint4*)(sm8 + W_HI_B);
        uint4* dlo = (uint4*)(sm8 + W_LO_B);
#pragma unroll
        for (int t = 0; t < 4; t++){
            int idx = r*256 + pt + 64*t;
            dhi[idx] = whi[idx];
            dlo[idx] = wlo[idx];
        }
    }
    barp(bid);                                                  // pair B8

    // ----- GEMM2 transposed -----
    gemm128q(Wh, Wl, Ah, Al, r, cb, lane, d);

    // ----- softmax + weighted xv sum -----
    {
        float bA = sbi2[rowA], bB = sbi2[rowB];
        float denA = 0, numA = 0, denB = 0, numB = 0;
#pragma unroll
        for (int t = 0; t < 8; t++){
            int jj = cb + t*8 + g4*2;
            float w0 = ex2(d[t][0] + bA), w1 = ex2(d[t][1] + bA);
            float w2 = ex2(d[t][2] + bB), w3 = ex2(d[t][3] + bB);
            float2 xA = *(float2*)(sxvT + rowA*XVS + jj);
            float2 xB = *(float2*)(sxvT + rowB*XVS + jj);
            denA += w0 + w1; numA += w0*xA.x + w1*xA.y;
            denB += w2 + w3; numB += w2*xB.x + w3*xB.y;
        }
        denA = qsum(denA); numA = qsum(numA);
        denB = qsum(denB); numB = qsum(numB);
        if (g4 == 0){
            sdn[ch*128 + rowA] = make_float2(denA, numA);
            sdn[ch*128 + rowB] = make_float2(denB, numB);
        }
        barp(bid);                                              // pair B9
        if (ch == 0 && g4 == 0){
            float2 a0 = sdn[rowA], a1 = sdn[128 + rowA];
            float2 b0 = sdn[rowB], b1 = sdn[128 + rowB];
            float oA = (a0.y + a1.y) / (a0.x + a1.x);
            float oB = (b0.y + b1.y) / (b0.x + b1.x);
            sxo[rowA] = oA; sxo[rowB] = oB;
            xout[(size_t)blockIdx.x*128 + rowA] = oA;
            xout[(size_t)blockIdx.x*128 + rowB] = oB;
        }
    }
    __syncthreads();                                            // FULL B10

    // ----- tail -----
    {
        int m = tid & 31, half = (tid>>5)&1, q = tid>>6;
        const float* er = e1 + m*257 + half*128 + q*16;
        const float* xo = sxo + q*16;
        float a = 0;
#pragma unroll
        for (int c2 = 0; c2 < 16; c2++) a = fmaf(xo[c2], er[c2], a);
        spart[(half*32 + m)*8 + q] = a;
    }
    __syncthreads();                                            // FULL B11
    if (tid < 64){
        float a = 0;
#pragma unroll
        for (int q = 0; q < 8; q++) a += spart[tid*8 + q];
        if (tid < 32) g_avec[(size_t)blockIdx.x*32 + tid] = a;
        else          g_bvec[(size_t)blockIdx.x*32 + (tid-32)] = a;
    }
}

// ---------------- K3: message MLP + position update ----------------
__global__ void __launch_bounds__(256, 2) k3_msg(
    const float* __restrict__ p, const float* __restrict__ e1,
    const float* __restrict__ x1b, const float* __restrict__ x2,
    const float* __restrict__ x2b,
    float* __restrict__ outp)
{
    extern __shared__ char sm8[];
    float* spij  = (float*)(sm8 + K3_SPIJ);
    float* snorm = (float*)(sm8 + K3_SNORM);
    float* ss    = (float*)(sm8 + K3_SS);
    float* spad  = (float*)(sm8 + K3_SPAD);
    float* sa    = (float*)(sm8 + K3_SA);
    float* se1c  = (float*)(sm8 + K3_SE1C);
    float* sx1b_ = (float*)(sm8 + K3_SX1B);
    float* sx2v  = (float*)(sm8 + K3_SX2V);

    const uint32_t sbase = smem_u32(sm8);
    const int tid = threadIdx.x, lane = tid & 31, warp = tid >> 5;
    const int n = blockIdx.x >> 7, i = blockIdx.x & 127;
    const bool pad_i = (p[(size_t)(n*128 + i)*4] == 0.0f);

    if (pad_i){
        if (tid == 0)
            *(float4*)(outp + (size_t)(n*128 + i)*4) = make_float4(0.f, 0.f, 0.f, 0.f);
        return;
    }

    const int g4 = lane & 3;
    const int rowA = warp*16 + (lane>>2), rowB = rowA + 8;

    if (tid < 128){
        int j = tid;
        float4 pi = *(const float4*)(p + (size_t)(n*128 + i)*4);
        float4 pj = *(const float4*)(p + (size_t)(n*128 + j)*4);
        float dx = pi.x - pj.x, dy = pi.y - pj.y, dz = pi.z - pj.z, dw = pi.w - pj.w;
        spij[j*4+0] = dx; spij[j*4+1] = dy; spij[j*4+2] = dz; spij[j*4+3] = dw;
        spad[j] = (pj.x != 0.0f) ? 1.0f : 0.0f;
        snorm[j] = dw*dw - dx*dx - dy*dy - dz*dz;
    }
    if (tid < 32){
        sa[tid]    = g_avec[(size_t)(n*128 + i)*32 + tid];
        se1c[tid]  = e1[tid*257 + 256];
        sx1b_[tid] = x1b[tid];
        sx2v[tid]  = x2[tid];
    }
    {
        const uint4* e2h = (const uint4*)g_e2hi;
        const uint4* e2l = (const uint4*)g_e2lo;
        uint4* d1h = (uint4*)(sm8 + K3_B1H);
        uint4* d1l = (uint4*)(sm8 + K3_B1L);
        for (int t = tid; t < 640; t += 256){
            d1h[t] = e2h[t];
            d1l[t] = e2l[t];
        }
        const uint4* x1h = (const uint4*)g_x1hi;
        const uint4* x1l = (const uint4*)g_x1lo;
        uint4* d2h = (uint4*)(sm8 + K3_B2H);
        uint4* d2l = (uint4*)(sm8 + K3_B2L);
        for (int t = tid; t < 512; t += 256){
            d2h[t] = x1h[t];
            d2l[t] = x1l[t];
        }
    }
    __syncthreads();

    // h32 tile: warp-owned rows
    const float* bv = g_bvec + (size_t)n*4096;
#pragma unroll
    for (int rr = 0; rr < 8; rr++){
        int e = rr*32 + lane;
        int row = warp*16 + (e >> 4);
        int mp = e & 15, m = mp*2;
        float nb = snorm[row];
        float2 bb = *(const float2*)(bv + row*32 + m);
        float h0 = fmaxf(sa[m]   + bb.x + nb*se1c[m],   0.0f);
        float h1 = fmaxf(sa[m+1] + bb.y + nb*se1c[m+1], 0.0f);
        uint32_t hi, lo;
        split2(h0, h1, hi, lo);
        *(uint32_t*)(sm8 + K3_A1H + row*80 + mp*4) = hi;
        *(uint32_t*)(sm8 + K3_A1L + row*80 + mp*4) = lo;
    }
    __syncwarp();

    // MMA1
    float d[16][4];
    gemm32(sbase + K3_A1H, sbase + K3_A1L, sbase + K3_B1H, sbase + K3_B1L, warp, lane, d);

    // relu -> LN (registers)
    {
        float s1A = 0, s2A = 0, s1B = 0, s2B = 0;
#pragma unroll
        for (int t = 0; t < 16; t++){
            float a0 = fmaxf(d[t][0], 0.0f), a1 = fmaxf(d[t][1], 0.0f);
            float b0 = fmaxf(d[t][2], 0.0f), b1 = fmaxf(d[t][3], 0.0f);
            d[t][0] = a0; d[t][1] = a1; d[t][2] = b0; d[t][3] = b1;
            s1A += a0 + a1; s2A += a0*a0 + a1*a1;
            s1B += b0 + b1; s2B += b0*b0 + b1*b1;
        }
        s1A = qsum(s1A); s2A = qsum(s2A); s1B = qsum(s1B); s2B = qsum(s2B);
        float muA = s1A*(1.0f/128.0f), vA = s2A*(1.0f/128.0f) - muA*muA;
        float muB = s1B*(1.0f/128.0f), vB = s2B*(1.0f/128.0f) - muB*muB;
        float rsA = rsqrtf(fmaxf(vA, 0.0f) + 1e-5f);
        float rsB = rsqrtf(fmaxf(vB, 0.0f) + 1e-5f);
#pragma unroll
        for (int t = 0; t < 16; t++){
            d[t][0] = (d[t][0]-muA)*rsA; d[t][1] = (d[t][1]-muA)*rsA;
            d[t][2] = (d[t][2]-muB)*rsB; d[t][3] = (d[t][3]-muB)*rsB;
        }
    }

    // MMA2: A from registers
    float d2[4][4];
    mma2_regA(d, sbase + K3_B2H, sbase + K3_B2L, lane, d2);

    // scores
    {
        float x2bv = x2b[0];
        float sA = 0, sB = 0;
#pragma unroll
        for (int t = 0; t < 4; t++){
            int c0 = t*8 + g4*2;
            float2 xb = *(float2*)(sx1b_ + c0);
            float2 xv = *(float2*)(sx2v + c0);
            sA += fmaxf(d2[t][0] + xb.x, 0.0f)*xv.x + fmaxf(d2[t][1] + xb.y, 0.0f)*xv.y;
            sB += fmaxf(d2[t][2] + xb.x, 0.0f)*xv.x + fmaxf(d2[t][3] + xb.y, 0.0f)*xv.y;
        }
        sA = qsum(sA); sB = qsum(sB);
        if (g4 == 0){
            ss[rowA] = fmaxf(sA + x2bv, 0.0f);
            ss[rowB] = fmaxf(sB + x2bv, 0.0f);
        }
    }
    __syncthreads();

    if (warp == 0){
        float m0 = fmaxf(fmaxf(ss[lane], ss[lane+32]), fmaxf(ss[lane+64], ss[lane+96]));
#pragma unroll
        for (int k = 16; k > 0; k >>= 1) m0 = fmaxf(m0, __shfl_xor_sync(0xffffffffu, m0, k));
        float den = 0, dx = 0, dy = 0, dz = 0, dw = 0, cnt = 0;
#pragma unroll
        for (int q2 = 0; q2 < 4; q2++){
            int b = lane + 32*q2;
            float w = __expf(ss[b] - m0);
            den += w;
            dx = fmaf(w, spij[b*4+0], dx);
            dy = fmaf(w, spij[b*4+1], dy);
            dz = fmaf(w, spij[b*4+2], dz);
            dw = fmaf(w, spij[b*4+3], dw);
            cnt += spad[b];
        }
        den = wsum(den); dx = wsum(dx); dy = wsum(dy);
        dz = wsum(dz);   dw = wsum(dw); cnt = wsum(cnt);
        if (lane == 0){
            float inv = 1.0f / (den * cnt);
            const float* pr = p + (size_t)(n*128 + i)*4;
            float* o = outp + (size_t)(n*128 + i)*4;
            float d4[4] = {dx, dy, dz, dw};
#pragma unroll
            for (int dd = 0; dd < 4; dd++){
                float pv = pr[dd];
                o[dd] = (pv == 0.0f) ? 0.0f : pv + d4[dd]*inv;
            }
        }
    }
}

extern "C" void kernel_launch(void* const* d_in, const int* in_sizes, int n_in,
                              void* d_out, int out_size){
    const float* x     = (const float*)d_in[0];
    const float* p     = (const float*)d_in[1];
    const float* U     = (const float*)d_in[2];
    const float* wq    = (const float*)d_in[3];
    const float* bq    = (const float*)d_in[4];
    const float* wk    = (const float*)d_in[5];
    const float* bk    = (const float*)d_in[6];
    const float* wv    = (const float*)d_in[7];
    const float* bv    = (const float*)d_in[8];
    const float* ln1_g = (const float*)d_in[9];
    const float* ln1_b = (const float*)d_in[10];
    const float* w1    = (const float*)d_in[11];
    const float* b1    = (const float*)d_in[12];
    const float* ln2_g = (const float*)d_in[13];
    const float* ln2_b = (const float*)d_in[14];
    const float* w2    = (const float*)d_in[15];
    const float* b2    = (const float*)d_in[16];
    const float* pe1   = (const float*)d_in[17];
    const float* pe2   = (const float*)d_in[18];
    const float* e1    = (const float*)d_in[19];
    const float* e2    = (const float*)d_in[20];
    const float* x1    = (const float*)d_in[21];
    const float* x1b   = (const float*)d_in[22];
    const float* x2    = (const float*)d_in[23];
    const float* x2b   = (const float*)d_in[24];
    float* out  = (float*)d_out;
    float* xout = out;
    float* newp = out + 16*128*128;

    cudaFuncSetAttribute(k2_attn, cudaFuncAttributeMaxDynamicSharedMemorySize, K2_SMEM);
    cudaFuncSetAttribute(k3_msg,  cudaFuncAttributeMaxDynamicSharedMemorySize, K3_SMEM);

    k0_prep<<<64, 256>>>(wq, wk, wv, w1, w2, pe2, e2, x1);
    k1_qkv<<<2048, 128>>>(x, bq, bk, bv);
    k2_attn<<<2048, 512, K2_SMEM>>>(U, p, ln1_g, ln1_b, b1, ln2_g, ln2_b, b2, pe1, e1, xout);
    k3_msg<<<2048, 256, K3_SMEM>>>(p, e1, x1b, x2, x2b, newp);
}